// round 17
// baseline (speedup 1.0000x reference)
#include <cuda_runtime.h>
#include <cuda_fp16.h>
#include <cstdint>

// Fused 9-layer MLP via mma.sync fp16 (HMMA), single-pass fp16, fp32 accum.
// N=262144, IN=39(pad64), H=256, OUT=4.
// R17 = R14 shape (64 rows/CTA, 128 thr, 4 warps, warp tile 64x64, 2 CTAs/SM)
// with WARP-AUTONOMOUS weight staging: warp w stages only W cols [64w,64w+64)
// using its own cp.async groups + per-thread wait_group -> ZERO barriers in
// the chunk loop. Only 2 __syncthreads per layer (around the A epilogue).
// Bias and w9 read directly from global (L2).

#define THREADS 128
#define M_TILE  64
#define NROWS   262144

// 30 chunks of [64 k][256 n] fp16 each (row-major, k-major rows)
__device__ __align__(256) __half g_w[30 * 16384];

// ---- smem byte layout ----
#define WBUF_SZ  33792              // per buf: 64*528 (4 warp slices interleaved)
#define SM_W     0                  // 2 bufs = 67584
#define SM_A     67584              // [64 rows][264 cols] fp16 = 33792
#define SM_X     101376             // [64 rows][72 cols] fp16 = 9216
#define SM_TOTAL 110592             // x2 CTAs = 221184 <= 227KB

#define ASTR 528     // A row stride bytes (264 fp16)
#define XSTR 144     // x row stride bytes (72 fp16)
#define WSTR 528     // W smem row stride bytes (data in first 512B)

// ---------- PTX helpers ----------
__device__ __forceinline__ uint32_t smem_u32(const void* p) {
    uint32_t a;
    asm("{ .reg .u64 t; cvta.to.shared.u64 t, %1; cvt.u32.u64 %0, t; }" : "=r"(a) : "l"(p));
    return a;
}
__device__ __forceinline__ void cpa16(uint8_t* s, const uint8_t* g) {
    uint32_t ss = smem_u32(s);
    asm volatile("cp.async.cg.shared.global [%0], [%1], 16;" :: "r"(ss), "l"(g));
}
__device__ __forceinline__ void cp_commit() { asm volatile("cp.async.commit_group;"); }
__device__ __forceinline__ void cp_wait0()  { asm volatile("cp.async.wait_group 0;"); }
__device__ __forceinline__ void cp_wait1()  { asm volatile("cp.async.wait_group 1;"); }

__device__ __forceinline__ void ldsm4(uint32_t* r, uint32_t addr) {
    asm volatile("ldmatrix.sync.aligned.m8n8.x4.shared.b16 {%0,%1,%2,%3}, [%4];"
                 : "=r"(r[0]), "=r"(r[1]), "=r"(r[2]), "=r"(r[3]) : "r"(addr));
}
__device__ __forceinline__ void ldsm4t(uint32_t* r, uint32_t addr) {
    asm volatile("ldmatrix.sync.aligned.m8n8.x4.trans.shared.b16 {%0,%1,%2,%3}, [%4];"
                 : "=r"(r[0]), "=r"(r[1]), "=r"(r[2]), "=r"(r[3]) : "r"(addr));
}
__device__ __forceinline__ void mma_f16(float* c, const uint32_t* a, uint32_t b0, uint32_t b1) {
    asm volatile(
        "mma.sync.aligned.m16n8k16.row.col.f32.f16.f16.f32 "
        "{%0,%1,%2,%3}, {%4,%5,%6,%7}, {%8,%9}, {%0,%1,%2,%3};"
        : "+f"(c[0]), "+f"(c[1]), "+f"(c[2]), "+f"(c[3])
        : "r"(a[0]), "r"(a[1]), "r"(a[2]), "r"(a[3]), "r"(b0), "r"(b1));
}
__device__ __forceinline__ uint32_t pack_h2(float v0, float v1) {
    __half h0 = __float2half_rn(v0);
    __half h1 = __float2half_rn(v1);
    return ((uint32_t)__half_as_ushort(h1) << 16) | __half_as_ushort(h0);
}

// ---------- prep: fp32 weights -> fp16 [k][n] chunks ----------
__global__ void __launch_bounds__(256) prep_kernel(
    const float* __restrict__ w1, const float* __restrict__ w2,
    const float* __restrict__ w3, const float* __restrict__ w4,
    const float* __restrict__ w5, const float* __restrict__ w6,
    const float* __restrict__ w7, const float* __restrict__ w8)
{
    int gid = blockIdx.x * 256 + threadIdx.x;   // 0 .. 491519
    int chunk = gid >> 14;
    int e = gid & 16383;
    int kl = e >> 8;
    int r  = e & 255;
    const float* src; int k0, Ksrc;
    if (chunk == 0)      { src = w1; k0 = 0;                 Ksrc = 39;  }
    else if (chunk < 5)  { src = w2; k0 = (chunk - 1) * 64;  Ksrc = 256; }
    else if (chunk < 9)  { src = w3; k0 = (chunk - 5) * 64;  Ksrc = 256; }
    else if (chunk < 13) { src = w4; k0 = (chunk - 9) * 64;  Ksrc = 256; }
    else if (chunk < 18) { src = w5; k0 = (chunk - 13) * 64; Ksrc = 295; }
    else if (chunk < 22) { src = w6; k0 = (chunk - 18) * 64; Ksrc = 256; }
    else if (chunk < 26) { src = w7; k0 = (chunk - 22) * 64; Ksrc = 256; }
    else                 { src = w8; k0 = (chunk - 26) * 64; Ksrc = 256; }
    int k = k0 + kl;
    float v = (k < Ksrc) ? src[k * 256 + r] : 0.0f;
    g_w[gid] = __float2half_rn(v);
}

// ---------- warp-private slice staging (no barriers) ----------
// warp `wid` stages cols [64*wid, 64*wid+64) of `chunk` into buffer `buf`.
// 64 rows x 128B = 512 cpa16 over 32 lanes (16 each), then commit.
__device__ __forceinline__ void stage_slice(uint8_t* sm, int buf, int chunk,
                                            int wid, int lane) {
    const uint8_t* src = (const uint8_t*)g_w + (size_t)chunk * 32768 + wid * 128;
    uint8_t* dst = sm + SM_W + buf * WBUF_SZ + wid * 128;
#pragma unroll
    for (int i = lane; i < 512; i += 32) {
        int row = i >> 3, j = i & 7;
        cpa16(dst + row * WSTR + j * 16, src + row * 512 + j * 16);
    }
    cp_commit();
}

// warp tile 64x64: C[4 mf][8 nf][4]; per ks: 4 ldsm4t(B) + 4 ldsm4(A), 32 mmas.
__device__ __forceinline__ void compute_chunk(
    float C[4][8][4],
    uint32_t a_base, int astr,
    uint32_t w_base,
    int lane, int col0w)
{
    const int quad = lane >> 3;
    const int qr   = lane & 7;
    const int arow_off = ((quad & 1) << 3) + qr;
    const int acol_off = (quad >> 1) << 3;
    const int brow_off = ((quad & 1) << 3) + qr;
    const int bcol_off = (quad >> 1) << 3;

#pragma unroll
    for (int ks = 0; ks < 4; ks++) {
        const int k0 = ks * 16;
        uint32_t b[4][4];
#pragma unroll
        for (int np = 0; np < 4; np++) {
            int ncol = col0w + np * 16 + bcol_off;
            ldsm4t(b[np], w_base + (uint32_t)((k0 + brow_off) * WSTR + ncol * 2));
        }
#pragma unroll
        for (int mf = 0; mf < 4; mf++) {
            uint32_t a[4];
            int row = mf * 16 + arow_off;
            ldsm4(a, a_base + (uint32_t)(row * astr + (k0 + acol_off) * 2));
#pragma unroll
            for (int np = 0; np < 4; np++)
#pragma unroll
                for (int ns = 0; ns < 2; ns++)
                    mma_f16(C[mf][np * 2 + ns], a, b[np][2 * ns], b[np][2 * ns + 1]);
        }
    }
}

__global__ void __launch_bounds__(THREADS, 2) mlp_mma_kernel(
    const float* __restrict__ x,
    const float* __restrict__ b1, const float* __restrict__ b2,
    const float* __restrict__ b3, const float* __restrict__ b4,
    const float* __restrict__ b5, const float* __restrict__ b6,
    const float* __restrict__ b7, const float* __restrict__ b8,
    const float* __restrict__ w9, const float* __restrict__ b9,
    float* __restrict__ out)
{
    extern __shared__ uint8_t sm[];
    const int tid  = threadIdx.x;
    const int wid  = tid >> 5;
    const int lane = tid & 31;
    const int col0w = wid * 64;          // warp n-slice (0/64/128/192)
    const int row0 = blockIdx.x * M_TILE;

    const uint32_t a_base = smem_u32(sm + SM_A);
    const uint32_t x_base = smem_u32(sm + SM_X);

    static const int CB[8]  = {0, 1, 5, 9, 13, 18, 22, 26};
    static const int NCK[8] = {1, 4, 4, 4, 5,  4,  4,  4};

    // warp-private: stage own slice of chunk 0 (group A)
    stage_slice(sm, 0, 0, wid, lane);

    // stage x tile (fp16) cooperatively via cp.async (group B)
    {
        const float* xg = x + (size_t)row0 * 39;
        __half* xh = (__half*)(sm + SM_X);
        // scalar conversion loads (global->reg->smem); small, done once
        for (int i = tid; i < M_TILE * 64; i += THREADS) {
            int r = i >> 6, k = i & 63;
            float v = (k < 39) ? xg[(size_t)r * 39 + k] : 0.0f;
            xh[r * 72 + k] = __float2half_rn(v);
        }
    }
    cp_wait0();          // drain this thread's chunk-0 slice loads
    __syncthreads();     // x tile visible to all warps

    const float* Bl[8] = {b1, b2, b3, b4, b5, b6, b7, b8};
    int bi = 0;

    for (int l = 0; l < 8; l++) {
        float C[4][8][4];
#pragma unroll
        for (int i = 0; i < 4; i++)
#pragma unroll
            for (int j = 0; j < 8; j++)
#pragma unroll
                for (int q = 0; q < 4; q++) C[i][j][q] = 0.0f;

        const int nck = NCK[l];
        for (int c = 0; c < nck; c++) {
            int nxt = (c + 1 < nck) ? (CB[l] + c + 1) : ((l < 7) ? CB[l + 1] : -1);
            if (nxt >= 0) { stage_slice(sm, bi ^ 1, nxt, wid, lane); cp_wait1(); }
            else          { cp_wait0(); }
            // no barrier: this warp reads only its own slice (cols 64w..64w+63)

            const uint32_t wh = smem_u32(sm + SM_W + bi * WBUF_SZ);
            const bool usex = (l == 0) || (l == 4 && c == 4);
            const uint32_t akoff = usex ? 0u : (uint32_t)(c * 128);
            compute_chunk(C,
                          (usex ? x_base : a_base) + akoff,
                          usex ? XSTR : ASTR,
                          wh, lane, col0w);
            bi ^= 1;
        }
        __syncthreads();   // all warps done READING A before it is rewritten

        if (l < 7) {
            const float* bias = Bl[l];
            // epilogue: bias + relu, write A in place (fp16)
#pragma unroll
            for (int mf = 0; mf < 4; mf++) {
#pragma unroll
                for (int nf = 0; nf < 8; nf++) {
                    int col = col0w + nf * 8 + 2 * (lane & 3);
                    int rA  = mf * 16 + (lane >> 2);
                    float b0v = __ldg(bias + col);
                    float b1v = __ldg(bias + col + 1);
                    float* cc = C[mf][nf];
                    float v0 = fmaxf(cc[0] + b0v, 0.0f);
                    float v1 = fmaxf(cc[1] + b1v, 0.0f);
                    float v2 = fmaxf(cc[2] + b0v, 0.0f);
                    float v3 = fmaxf(cc[3] + b1v, 0.0f);
                    uint32_t off  = (uint32_t)(rA * ASTR + col * 2);
                    uint32_t off2 = off + 8u * ASTR;
                    *(uint32_t*)(sm + SM_A + off)  = pack_h2(v0, v1);
                    *(uint32_t*)(sm + SM_A + off2) = pack_h2(v2, v3);
                }
            }
            __syncthreads();   // new A visible before next layer reads
        } else {
            // final epilogue: relu(h)+bias, then x w9 (256->4) via smem atomics
            const float* bias = Bl[7];
            float* scr = (float*)sm;            // 256 floats (W bufs dead now)
            for (int i = tid; i < 256; i += THREADS) scr[i] = 0.0f;
            __syncthreads();
            float p[8][4];
#pragma unroll
            for (int i = 0; i < 8; i++)
#pragma unroll
                for (int j = 0; j < 4; j++) p[i][j] = 0.0f;
#pragma unroll
            for (int mf = 0; mf < 4; mf++) {
#pragma unroll
                for (int nf = 0; nf < 8; nf++) {
                    int col = col0w + nf * 8 + 2 * (lane & 3);
                    float b0v = __ldg(bias + col);
                    float b1v = __ldg(bias + col + 1);
                    float* cc = C[mf][nf];
                    float v0 = fmaxf(cc[0] + b0v, 0.0f);
                    float v1 = fmaxf(cc[1] + b1v, 0.0f);
                    float v2 = fmaxf(cc[2] + b0v, 0.0f);
                    float v3 = fmaxf(cc[3] + b1v, 0.0f);
                    const float* wc0 = w9 + col * 4;
                    const float* wc1 = w9 + (col + 1) * 4;
#pragma unroll
                    for (int j = 0; j < 4; j++) {
                        p[2 * mf][j]     += v0 * wc0[j] + v1 * wc1[j];
                        p[2 * mf + 1][j] += v2 * wc0[j] + v3 * wc1[j];
                    }
                }
            }
#pragma unroll
            for (int rr = 0; rr < 8; rr++) {
                int row = (rr >> 1) * 16 + (rr & 1) * 8 + (lane >> 2);
#pragma unroll
                for (int j = 0; j < 4; j++)
                    atomicAdd(scr + row * 4 + j, p[rr][j]);
            }
            __syncthreads();
            for (int i = tid; i < 256; i += THREADS)
                out[(size_t)(row0 + (i >> 2)) * 4 + (i & 3)] = scr[i] + b9[i & 3];
        }
    }
}

extern "C" void kernel_launch(void* const* d_in, const int* in_sizes, int n_in,
                              void* d_out, int out_size)
{
    const float* x  = (const float*)d_in[0];
    const float* w1 = (const float*)d_in[1],  *b1 = (const float*)d_in[2];
    const float* w2 = (const float*)d_in[3],  *b2 = (const float*)d_in[4];
    const float* w3 = (const float*)d_in[5],  *b3 = (const float*)d_in[6];
    const float* w4 = (const float*)d_in[7],  *b4 = (const float*)d_in[8];
    const float* w5 = (const float*)d_in[9],  *b5 = (const float*)d_in[10];
    const float* w6 = (const float*)d_in[11], *b6 = (const float*)d_in[12];
    const float* w7 = (const float*)d_in[13], *b7 = (const float*)d_in[14];
    const float* w8 = (const float*)d_in[15], *b8 = (const float*)d_in[16];
    const float* w9 = (const float*)d_in[17], *b9 = (const float*)d_in[18];
    float* out = (float*)d_out;

    prep_kernel<<<1920, 256>>>(w1, w2, w3, w4, w5, w6, w7, w8);

    cudaFuncSetAttribute(mlp_mma_kernel,
                         cudaFuncAttributeMaxDynamicSharedMemorySize, SM_TOTAL);
    mlp_mma_kernel<<<NROWS / M_TILE, THREADS, SM_TOTAL>>>(
        x, b1, b2, b3, b4, b5, b6, b7, b8, w9, b9, out);
}